// round 13
// baseline (speedup 1.0000x reference)
#include <cuda_runtime.h>
#include <math.h>

#define Nn    1152
#define Dd    64
#define Bb    16
#define Tt    1024
#define NSKEW 2016
#define CONDD 1152
#define MP    68
#define MPT   68
#define P1S   68
#define P2SY  68
#define P2SU  132
#define PW    16
#define PSTR  1153   // panel column stride (odd -> conflict-free strided V reads)

typedef unsigned long long ull;

// ------------------ device scratch (no allocations allowed) ------------------
__device__ __align__(16) float g_At[Dd * Nn];       // Householder vectors, column j contiguous
__device__ __align__(16) float g_tau[Dd];
__device__ __align__(16) float g_T [4 * PW * PW];   // compact-WY T per panel
__device__ __align__(16) float g_U [Nn * Dd];       // U  [n][d]
__device__ __align__(16) float g_Ut[Dd * Nn];       // U^T [d][n]
__device__ __align__(16) float g_V [Bb * NSKEW];    // silu(cond) @ W^T + b
__device__ __align__(16) float g_RmI[Bb * Dd * Dd]; // R - I per batch, row-major [d][e]
__device__ __align__(16) float g_Y [Bb * Tt * Dd];  // (X U)(R-I)

// ------------------ packed f32x2 helpers (Blackwell FFMA2) ------------------
static __device__ __forceinline__ ull pack2(float x, float y) {
    ull r; asm("mov.b64 %0, {%1, %2};" : "=l"(r) : "f"(x), "f"(y)); return r;
}
static __device__ __forceinline__ void unpack2(ull p, float& x, float& y) {
    asm("mov.b64 {%0, %1}, %2;" : "=f"(x), "=f"(y) : "l"(p));
}
static __device__ __forceinline__ ull fma2(ull a, ull b, ull c) {
    ull d; asm("fma.rn.f32x2 %0, %1, %2, %3;" : "=l"(d) : "l"(a), "l"(b), "l"(c)); return d;
}

// =============================================================================
// Kernel 1a: panel factorization (sgeqrf panel of 16, LAPACK sign convention).
// One block, 256 threads; panel in smem. Writes V (scaled reflectors + R block),
// tau, and compact-WY T for this panel.
// =============================================================================
__global__ void __launch_bounds__(256) k_panel(const float* __restrict__ P, int p) {
    extern __shared__ float V[];           // [PW][PSTR] panel, column-major
    __shared__ float sred[8];
    __shared__ float s_tau, s_scale;
    __shared__ float tau16[PW];
    __shared__ float Tm[PW * PW];
    __shared__ float Sm[PW * PW];
    const int tid = threadIdx.x, lane = tid & 31, wid = tid >> 5;
    const int j0 = p * PW;

    // first panel also transposes P into g_At
    if (p == 0) {
        for (int idx = tid; idx < Nn * Dd; idx += 256) {
            int i = idx >> 6, j = idx & 63;
            g_At[j * Nn + i] = P[idx];
        }
        __syncthreads();
    }

    // ---- load panel into smem ----
    for (int idx = tid; idx < PW * Nn; idx += 256) {
        int c = idx / Nn, i = idx - c * Nn;
        V[c * PSTR + i] = g_At[(j0 + c) * Nn + i];
    }
    if (tid < PW * PW) { Tm[tid] = 0.f; Sm[tid] = 0.f; }
    __syncthreads();

    // ---- factor panel (right-looking, 16 steps) ----
    for (int jj = 0; jj < PW; ++jj) {
        const int j = j0 + jj;
        float* col = V + jj * PSTR;
        float ss = 0.f;
        for (int i = j + 1 + tid; i < Nn; i += 256) { float a = col[i]; ss += a * a; }
        #pragma unroll
        for (int o = 16; o; o >>= 1) ss += __shfl_xor_sync(0xffffffffu, ss, o);
        if (lane == 0) sred[wid] = ss;
        __syncthreads();
        if (wid == 0) {
            float q = (lane < 8) ? sred[lane] : 0.f;
            #pragma unroll
            for (int o = 4; o; o >>= 1) q += __shfl_xor_sync(0xffffffffu, q, o);
            if (lane == 0) {
                float alpha = col[j];
                float nrm = sqrtf(alpha * alpha + q);
                float beta = (alpha >= 0.f) ? -nrm : nrm;   // LAPACK convention
                float tau = (beta - alpha) / beta;
                g_tau[j] = tau; tau16[jj] = tau;
                s_tau = tau; s_scale = 1.f / (alpha - beta);
                col[j] = beta;
            }
        }
        __syncthreads();
        const float tau = s_tau, scl = s_scale;
        for (int i = j + 1 + tid; i < Nn; i += 256) col[i] *= scl;
        __syncthreads();
        // trailing panel columns, warp per column
        for (int k = jj + 1 + wid; k < PW; k += 8) {
            float* ck = V + k * PSTR;
            float dp = (lane == 0) ? ck[j] : 0.f;
            for (int i = j + 1 + lane; i < Nn; i += 32) dp += col[i] * ck[i];
            #pragma unroll
            for (int o = 16; o; o >>= 1) dp += __shfl_xor_sync(0xffffffffu, dp, o);
            dp *= tau;
            if (lane == 0) ck[j] -= dp;
            for (int i = j + 1 + lane; i < Nn; i += 32) ck[i] -= dp * col[i];
        }
        __syncthreads();
    }

    // ---- write panel back (R block + reflector vectors) ----
    for (int idx = tid; idx < PW * Nn; idx += 256) {
        int c = idx / Nn, i = idx - c * Nn;
        g_At[(j0 + c) * Nn + i] = V[c * PSTR + i];
    }
    __syncthreads();

    // ---- clean V: zeros above diag, unit diag (rows 0..63 suffice) ----
    for (int t = tid; t < PW * 64; t += 256) {
        int c = t >> 6, i = t & 63;
        int d = j0 + c;
        if (i < d)       V[c * PSTR + i] = 0.f;
        else if (i == d) V[c * PSTR + i] = 1.f;
    }
    __syncthreads();

    // ---- S[a][b] = v_a . v_b (a < b), warp per pair ----
    for (int pr = wid; pr < PW * PW; pr += 8) {
        int a = pr >> 4, b2 = pr & 15;
        if (a < b2) {
            float dp = 0.f;
            for (int i = j0 + a + lane; i < Nn; i += 32)
                dp += V[a * PSTR + i] * V[b2 * PSTR + i];
            #pragma unroll
            for (int o = 16; o; o >>= 1) dp += __shfl_xor_sync(0xffffffffu, dp, o);
            if (lane == 0) Sm[a * PW + b2] = dp;
        }
    }
    __syncthreads();

    // ---- build T (dlarft forward columnwise), warp 0 ----
    if (wid == 0) {
        for (int jj = 0; jj < PW; ++jj) {
            float t = 0.f;
            if (lane < jj) {
                float acc = 0.f;
                for (int m = 0; m < jj; ++m) acc += Tm[lane * PW + m] * Sm[m * PW + jj];
                t = -tau16[jj] * acc;
            }
            __syncwarp();
            if (lane < jj) Tm[lane * PW + jj] = t;
            if (lane == jj) Tm[jj * PW + jj] = tau16[jj];
            __syncwarp();
        }
    }
    __syncthreads();
    if (tid < PW * PW) g_T[p * PW * PW + tid] = Tm[tid];
}

// =============================================================================
// Kernel 1a': trailing update, one block per trailing column.
// c <- c - V * T^T * (V^T c), column cached in smem, V read from L2.
// =============================================================================
__global__ void __launch_bounds__(256) k_trail(int p) {
    __shared__ float c[Nn];
    __shared__ float w[PW], w2[PW];
    const int tid = threadIdx.x, lane = tid & 31, wid = tid >> 5;
    const int j0 = p * PW;
    const int colg = j0 + PW + blockIdx.x;
    float* cg = g_At + (size_t)colg * Nn;

    for (int i = tid; i < Nn; i += 256) c[i] = cg[i];
    __syncthreads();

    // w[a] = v_a . c  (v unit diag at j0+a, scaled entries below)
    for (int a = wid; a < PW; a += 8) {
        const int j = j0 + a;
        const float* v = g_At + (size_t)j * Nn;
        float dp = (lane == 0) ? c[j] : 0.f;
        for (int i = j + 1 + lane; i < Nn; i += 32) dp += v[i] * c[i];
        #pragma unroll
        for (int o = 16; o; o >>= 1) dp += __shfl_xor_sync(0xffffffffu, dp, o);
        if (lane == 0) w[a] = dp;
    }
    __syncthreads();
    // w2[b] = sum_{a<=b} T[a][b] w[a]   (T^T w)
    if (tid < PW) {
        const float* Tp = g_T + p * PW * PW;
        float acc = 0.f;
        for (int a = 0; a <= tid; ++a) acc += Tp[a * PW + tid] * w[a];
        w2[tid] = acc;
    }
    __syncthreads();
    // c -= V w2 : rows j0..j0+15 triangular, rows >= j0+16 full
    if (tid < PW) {
        int i = j0 + tid;
        float acc = w2[tid];    // a == tid term (v = 1)
        for (int a = 0; a < tid; ++a) acc += g_At[(size_t)(j0 + a) * Nn + i] * w2[a];
        c[i] -= acc;
    }
    for (int i = j0 + PW + tid; i < Nn; i += 256) {
        float acc = 0.f;
        #pragma unroll
        for (int a = 0; a < PW; ++a) acc += g_At[(size_t)(j0 + a) * Nn + i] * w2[a];
        c[i] -= acc;
    }
    __syncthreads();
    for (int i = j0 + tid; i < Nn; i += 256) cg[i] = c[i];
}

// =============================================================================
// Kernel 1b: form Q (sorgqr), one block per Q column, compact-WY panel apply.
// =============================================================================
__global__ void __launch_bounds__(256) k_orgqr() {
    __shared__ float q[Nn];
    __shared__ float w[PW], w2[PW];
    __shared__ float sred[8];
    __shared__ float s_rho;
    const int tid = threadIdx.x, lane = tid & 31, wid = tid >> 5;
    const int k = blockIdx.x;
    const int pk = k >> 4;

    for (int i = tid; i < Nn; i += 256) q[i] = (i == k) ? 1.f : 0.f;
    __syncthreads();

    // ---- boundary panel: sequential reflectors j = k .. pk*16 ----
    for (int j = k; j >= pk * PW; --j) {
        const float* v = g_At + (size_t)j * Nn;
        float dp = (tid == 0) ? q[j] : 0.f;
        for (int i = j + 1 + tid; i < Nn; i += 256) dp += v[i] * q[i];
        #pragma unroll
        for (int o = 16; o; o >>= 1) dp += __shfl_xor_sync(0xffffffffu, dp, o);
        if (lane == 0) sred[wid] = dp;
        __syncthreads();
        if (tid == 0) {
            float s = sred[0] + sred[1] + sred[2] + sred[3]
                    + sred[4] + sred[5] + sred[6] + sred[7];
            s_rho = s * g_tau[j];
        }
        __syncthreads();
        const float rho = s_rho;
        if (tid == 0) q[j] -= rho;
        for (int i = j + 1 + tid; i < Nn; i += 256) q[i] -= rho * v[i];
        __syncthreads();
    }

    // ---- full panels below: q -= V (T (V^T q)) ----
    for (int p = pk - 1; p >= 0; --p) {
        const int j0 = p * PW;
        for (int a = wid; a < PW; a += 8) {
            int j = j0 + a;
            const float* v = g_At + (size_t)j * Nn;
            float dp = (lane == 0) ? q[j] : 0.f;
            for (int i = j + 1 + lane; i < Nn; i += 32) dp += v[i] * q[i];
            #pragma unroll
            for (int o = 16; o; o >>= 1) dp += __shfl_xor_sync(0xffffffffu, dp, o);
            if (lane == 0) w[a] = dp;
        }
        __syncthreads();
        if (tid < PW) {
            const float* Tp = g_T + p * PW * PW;
            float acc = 0.f;
            for (int b2 = tid; b2 < PW; ++b2) acc += Tp[tid * PW + b2] * w[b2];
            w2[tid] = acc;
        }
        __syncthreads();
        if (tid < PW) {
            int i = j0 + tid;
            float acc = w2[tid];
            for (int a = 0; a < tid; ++a) acc += g_At[(size_t)(j0 + a) * Nn + i] * w2[a];
            q[i] -= acc;
        }
        for (int i = j0 + PW + tid; i < Nn; i += 256) {
            float acc = 0.f;
            #pragma unroll
            for (int a = 0; a < PW; ++a) acc += g_At[(size_t)(j0 + a) * Nn + i] * w2[a];
            q[i] -= acc;
        }
        __syncthreads();
    }

    for (int i = tid; i < Nn; i += 256) {
        float val = q[i];
        g_Ut[k * Nn + i] = val;
        g_U[i * Dd + k]  = val;
    }
}

// =============================================================================
// Kernel 2: g_V[b][r] = dot(W[r], silu(cond[b])) + bias[r]
// =============================================================================
__global__ void __launch_bounds__(256) k_v(const float* __restrict__ cond,
                                           const float* __restrict__ W,
                                           const float* __restrict__ bias) {
    extern __shared__ float S[];   // [16][1152] silu(cond)
    const int tid = threadIdx.x, lane = tid & 31, wid = tid >> 5;
    for (int i = tid; i < Bb * CONDD; i += 256) {
        float c = cond[i];
        S[i] = c / (1.f + expf(-c));
    }
    __syncthreads();

    int r = blockIdx.x * 8 + wid;
    const float* wr = W + (size_t)r * CONDD;
    float acc[16];
    #pragma unroll
    for (int b = 0; b < 16; b++) acc[b] = 0.f;
    for (int c0 = 0; c0 < CONDD; c0 += 32) {
        float wv = wr[c0 + lane];
        #pragma unroll
        for (int b = 0; b < 16; b++) acc[b] += wv * S[b * CONDD + c0 + lane];
    }
    #pragma unroll
    for (int b = 0; b < 16; b++) {
        #pragma unroll
        for (int o = 16; o; o >>= 1) acc[b] += __shfl_xor_sync(0xffffffffu, acc[b], o);
    }
    if (lane == 0) {
        float bv = bias[r];
        #pragma unroll
        for (int b = 0; b < 16; b++) g_V[b * NSKEW + r] = acc[b] + bv;
    }
}

// =============================================================================
// Kernel 3: expm per batch (scaling & squaring + Taylor-Horner K=8).
// 16 blocks x 256 threads, 4x4 register tile per thread, FFMA2 inner loops.
// Horner uses skew-symmetry: A[r][d] = -As[d][r]; sign folded into -invk.
// =============================================================================
static __device__ __forceinline__ void mm_horner(float* __restrict__ out,
                                                 const float* __restrict__ As,
                                                 const float* __restrict__ X,
                                                 float invk, int r0, int c0) {
    ull acc[4][2] = {};
    #pragma unroll 4
    for (int d = 0; d < 64; ++d) {
        float4 a4 = *(const float4*)(As + d * MP + r0);        // As[d][r] = -A[r][d]
        ulonglong2 bv = *(const ulonglong2*)(X + d * MP + c0);
        ull a0 = pack2(a4.x, a4.x), a1 = pack2(a4.y, a4.y);
        ull a2 = pack2(a4.z, a4.z), a3 = pack2(a4.w, a4.w);
        acc[0][0] = fma2(a0, bv.x, acc[0][0]); acc[0][1] = fma2(a0, bv.y, acc[0][1]);
        acc[1][0] = fma2(a1, bv.x, acc[1][0]); acc[1][1] = fma2(a1, bv.y, acc[1][1]);
        acc[2][0] = fma2(a2, bv.x, acc[2][0]); acc[2][1] = fma2(a2, bv.y, acc[2][1]);
        acc[3][0] = fma2(a3, bv.x, acc[3][0]); acc[3][1] = fma2(a3, bv.y, acc[3][1]);
    }
    const float nk = -invk;   // negate to undo the transposed-skew sign
    #pragma unroll
    for (int m = 0; m < 4; ++m) {
        float s0, s1, s2, s3;
        unpack2(acc[m][0], s0, s1);
        unpack2(acc[m][1], s2, s3);
        float4 o;
        o.x = nk * s0 + ((r0 + m == c0 + 0) ? 1.f : 0.f);
        o.y = nk * s1 + ((r0 + m == c0 + 1) ? 1.f : 0.f);
        o.z = nk * s2 + ((r0 + m == c0 + 2) ? 1.f : 0.f);
        o.w = nk * s3 + ((r0 + m == c0 + 3) ? 1.f : 0.f);
        *(float4*)(out + (r0 + m) * MP + c0) = o;
    }
}

static __device__ __forceinline__ void mm_sq(float* __restrict__ out,
                                             const float* __restrict__ XT,
                                             const float* __restrict__ X,
                                             int r0, int c0) {
    ull acc[4][2] = {};
    #pragma unroll 4
    for (int d = 0; d < 64; ++d) {
        float4 a4 = *(const float4*)(XT + d * MPT + r0);       // X[r0..r0+3][d]
        ulonglong2 bv = *(const ulonglong2*)(X + d * MP + c0);
        ull a0 = pack2(a4.x, a4.x), a1 = pack2(a4.y, a4.y);
        ull a2 = pack2(a4.z, a4.z), a3 = pack2(a4.w, a4.w);
        acc[0][0] = fma2(a0, bv.x, acc[0][0]); acc[0][1] = fma2(a0, bv.y, acc[0][1]);
        acc[1][0] = fma2(a1, bv.x, acc[1][0]); acc[1][1] = fma2(a1, bv.y, acc[1][1]);
        acc[2][0] = fma2(a2, bv.x, acc[2][0]); acc[2][1] = fma2(a2, bv.y, acc[2][1]);
        acc[3][0] = fma2(a3, bv.x, acc[3][0]); acc[3][1] = fma2(a3, bv.y, acc[3][1]);
    }
    #pragma unroll
    for (int m = 0; m < 4; ++m) {
        float s0, s1, s2, s3;
        unpack2(acc[m][0], s0, s1);
        unpack2(acc[m][1], s2, s3);
        *(float4*)(out + (r0 + m) * MP + c0) = make_float4(s0, s1, s2, s3);
    }
}

__global__ void __launch_bounds__(256) k_expm() {
    extern __shared__ float sm[];
    float* As = sm;                     // 64*68
    float* X0 = As + 64 * MP;
    float* X1 = X0 + 64 * MP;
    float* XT = X1 + 64 * MP;
    __shared__ float rowsum[64];
    __shared__ int s_s;
    const int tid = threadIdx.x;
    const int r0 = (tid >> 4) * 4, c0 = (tid & 15) * 4;
    const int b = blockIdx.x;
    const float* v = g_V + b * NSKEW;

    for (int t = tid; t < 4096; t += 256) {
        int i = t >> 6, j = t & 63;
        float val = 0.f;
        if (i < j)      val =  v[i * (127 - i) / 2 + (j - i - 1)];
        else if (i > j) val = -v[j * (127 - j) / 2 + (i - j - 1)];
        As[i * MP + j] = val;
    }
    __syncthreads();
    if (tid < 64) {
        float s = 0.f;
        for (int j = 0; j < 64; j++) s += fabsf(As[tid * MP + j]);
        rowsum[tid] = s;
    }
    __syncthreads();
    if (tid == 0) {
        float nrm = 0.f;
        for (int i = 0; i < 64; i++) nrm = fmaxf(nrm, rowsum[i]);
        int s = 0; float nn = nrm;
        while (nn > 0.5f && s < 40) { nn *= 0.5f; s++; }
        s_s = s;
    }
    __syncthreads();
    const int s = s_s;
    const float sc = exp2f((float)(-s));
    for (int t = tid; t < 4096; t += 256) { int i = t >> 6, j = t & 63; As[i * MP + j] *= sc; }
    __syncthreads();

    for (int t = tid; t < 4096; t += 256) {
        int i = t >> 6, j = t & 63;
        X0[i * MP + j] = ((i == j) ? 1.f : 0.f) + As[i * MP + j] * 0.125f;
    }
    float* Xa = X0; float* Xb = X1;
    for (int k = 7; k >= 1; --k) {
        __syncthreads();
        mm_horner(Xb, As, Xa, 1.f / (float)k, r0, c0);
        float* t = Xa; Xa = Xb; Xb = t;
    }
    for (int q = 0; q < s; q++) {
        __syncthreads();
        for (int t = tid; t < 4096; t += 256) {      // XT[j][i] = Xa[i][j]
            int i = t >> 6, j = t & 63;
            XT[j * MPT + i] = Xa[i * MP + j];
        }
        __syncthreads();
        mm_sq(Xb, XT, Xa, r0, c0);
        float* t = Xa; Xa = Xb; Xb = t;
    }
    __syncthreads();
    for (int t = tid; t < 4096; t += 256) {
        int i = t >> 6, j = t & 63;
        g_RmI[b * 4096 + t] = Xa[i * MP + j] - ((i == j) ? 1.f : 0.f);
    }
}

// =============================================================================
// Kernel 4: Y = (X U)(R - I).  64-row tiles, 256 blocks, 256 threads.
// =============================================================================
__global__ void __launch_bounds__(256) k_p1(const float* __restrict__ X,
                                            float* __restrict__ Y) {
    extern __shared__ float sm[];
    float* XsT = sm;                 // [64][68]  XsT[k][r]
    float* Us  = sm + 64 * P1S;      // [64][68]  Us[k][c]
    float* Ms  = Us + 64 * P1S;      // [64][68]  Ms[d][e]

    const int tid = threadIdx.x;
    const int rg = tid >> 4, cg = tid & 15;
    const int r0 = rg * 4, c0 = cg * 4;
    const size_t rowbase = (size_t)blockIdx.x * 64;
    const float* Xg = X + rowbase * Nn;
    const int b = blockIdx.x >> 4;

    const float* Mg = g_RmI + b * 4096;
    for (int i = tid; i < 4096; i += 256) {
        int d = i >> 6, e = i & 63;
        Ms[d * P1S + e] = Mg[i];
    }

    ull acc[4][2] = {};
    for (int kc = 0; kc < Nn; kc += 64) {
        __syncthreads();
        #pragma unroll
        for (int it = 0; it < 4; ++it) {
            int f4 = tid + 256 * it;
            int r  = f4 >> 4;
            int kq = (f4 & 15) * 4;
            float4 v = *(const float4*)(Xg + (size_t)r * Nn + kc + kq);
            XsT[(kq + 0) * P1S + r] = v.x;
            XsT[(kq + 1) * P1S + r] = v.y;
            XsT[(kq + 2) * P1S + r] = v.z;
            XsT[(kq + 3) * P1S + r] = v.w;
        }
        #pragma unroll
        for (int it = 0; it < 4; ++it) {
            int f4 = tid + 256 * it;
            int kk = f4 >> 4;
            int dq = (f4 & 15) * 4;
            float4 v = *(const float4*)(g_U + (size_t)(kc + kk) * Dd + dq);
            *(float4*)(Us + kk * P1S + dq) = v;
        }
        __syncthreads();
        #pragma unroll 4
        for (int k = 0; k < 64; ++k) {
            float4 xv = *(const float4*)(XsT + k * P1S + r0);
            ulonglong2 uv = *(const ulonglong2*)(Us + k * P1S + c0);
            ull x0 = pack2(xv.x, xv.x), x1 = pack2(xv.y, xv.y);
            ull x2 = pack2(xv.z, xv.z), x3 = pack2(xv.w, xv.w);
            acc[0][0] = fma2(x0, uv.x, acc[0][0]); acc[0][1] = fma2(x0, uv.y, acc[0][1]);
            acc[1][0] = fma2(x1, uv.x, acc[1][0]); acc[1][1] = fma2(x1, uv.y, acc[1][1]);
            acc[2][0] = fma2(x2, uv.x, acc[2][0]); acc[2][1] = fma2(x2, uv.y, acc[2][1]);
            acc[3][0] = fma2(x3, uv.x, acc[3][0]); acc[3][1] = fma2(x3, uv.y, acc[3][1]);
        }
    }
    __syncthreads();
    float* ZsT = XsT;
    #pragma unroll
    for (int m = 0; m < 4; ++m) {
        float a0, a1;
        unpack2(acc[m][0], a0, a1);
        ZsT[(c0 + 0) * P1S + r0 + m] = a0;
        ZsT[(c0 + 1) * P1S + r0 + m] = a1;
        unpack2(acc[m][1], a0, a1);
        ZsT[(c0 + 2) * P1S + r0 + m] = a0;
        ZsT[(c0 + 3) * P1S + r0 + m] = a1;
    }
    __syncthreads();
    ull yac[4][2] = {};
    #pragma unroll 4
    for (int d = 0; d < 64; ++d) {
        float4 zv = *(const float4*)(ZsT + d * P1S + r0);
        ulonglong2 mv = *(const ulonglong2*)(Ms + d * P1S + c0);
        ull z0 = pack2(zv.x, zv.x), z1 = pack2(zv.y, zv.y);
        ull z2 = pack2(zv.z, zv.z), z3 = pack2(zv.w, zv.w);
        yac[0][0] = fma2(z0, mv.x, yac[0][0]); yac[0][1] = fma2(z0, mv.y, yac[0][1]);
        yac[1][0] = fma2(z1, mv.x, yac[1][0]); yac[1][1] = fma2(z1, mv.y, yac[1][1]);
        yac[2][0] = fma2(z2, mv.x, yac[2][0]); yac[2][1] = fma2(z2, mv.y, yac[2][1]);
        yac[3][0] = fma2(z3, mv.x, yac[3][0]); yac[3][1] = fma2(z3, mv.y, yac[3][1]);
    }
    #pragma unroll
    for (int m = 0; m < 4; ++m) {
        float e0, e1, e2, e3;
        unpack2(yac[m][0], e0, e1);
        unpack2(yac[m][1], e2, e3);
        *(float4*)(Y + (rowbase + r0 + m) * Dd + c0) = make_float4(e0, e1, e2, e3);
    }
}

// =============================================================================
// Kernel 5: out = X + Y U^T.  Block tile 64 rows x 128 n-cols; grid (9, 256).
// =============================================================================
__global__ void __launch_bounds__(256) k_p2(const float* __restrict__ X,
                                            const float* __restrict__ Y,
                                            float* __restrict__ out) {
    extern __shared__ float sm[];
    float* YsT = sm;                 // [64][68]
    float* Uts = sm + 64 * P2SY;     // [64][132]

    const int tid = threadIdx.x;
    const int rg = tid >> 4, cg = tid & 15;
    const int r0 = rg * 4;
    const int n0 = cg * 8;
    const size_t rowbase = (size_t)blockIdx.y * 64;
    const int nbase = blockIdx.x * 128;

    #pragma unroll
    for (int it = 0; it < 4; ++it) {
        int f4 = tid + 256 * it;
        int r  = f4 >> 4;
        int dq = (f4 & 15) * 4;
        float4 v = *(const float4*)(Y + (rowbase + r) * Dd + dq);
        YsT[(dq + 0) * P2SY + r] = v.x;
        YsT[(dq + 1) * P2SY + r] = v.y;
        YsT[(dq + 2) * P2SY + r] = v.z;
        YsT[(dq + 3) * P2SY + r] = v.w;
    }
    #pragma unroll
    for (int it = 0; it < 8; ++it) {
        int f4 = tid + 256 * it;
        int d  = f4 >> 5;
        int nq = (f4 & 31) * 4;
        float4 v = *(const float4*)(g_Ut + (size_t)d * Nn + nbase + nq);
        *(float4*)(Uts + d * P2SU + nq) = v;
    }
    __syncthreads();

    ull acc[4][4] = {};
    #pragma unroll 4
    for (int d = 0; d < 64; ++d) {
        float4 yv = *(const float4*)(YsT + d * P2SY + r0);
        ulonglong2 u0 = *(const ulonglong2*)(Uts + d * P2SU + n0);
        ulonglong2 u1 = *(const ulonglong2*)(Uts + d * P2SU + n0 + 4);
        ull y0 = pack2(yv.x, yv.x), y1 = pack2(yv.y, yv.y);
        ull y2 = pack2(yv.z, yv.z), y3 = pack2(yv.w, yv.w);
        acc[0][0] = fma2(y0, u0.x, acc[0][0]); acc[0][1] = fma2(y0, u0.y, acc[0][1]);
        acc[0][2] = fma2(y0, u1.x, acc[0][2]); acc[0][3] = fma2(y0, u1.y, acc[0][3]);
        acc[1][0] = fma2(y1, u0.x, acc[1][0]); acc[1][1] = fma2(y1, u0.y, acc[1][1]);
        acc[1][2] = fma2(y1, u1.x, acc[1][2]); acc[1][3] = fma2(y1, u1.y, acc[1][3]);
        acc[2][0] = fma2(y2, u0.x, acc[2][0]); acc[2][1] = fma2(y2, u0.y, acc[2][1]);
        acc[2][2] = fma2(y2, u1.x, acc[2][2]); acc[2][3] = fma2(y2, u1.y, acc[2][3]);
        acc[3][0] = fma2(y3, u0.x, acc[3][0]); acc[3][1] = fma2(y3, u0.y, acc[3][1]);
        acc[3][2] = fma2(y3, u1.x, acc[3][2]); acc[3][3] = fma2(y3, u1.y, acc[3][3]);
    }

    #pragma unroll
    for (int m = 0; m < 4; ++m) {
        const size_t row = rowbase + r0 + m;
        const float* xr = X + row * Nn + nbase + n0;
        float* orow = out + row * Nn + nbase + n0;
        float4 xa = *(const float4*)(xr);
        float4 xb = *(const float4*)(xr + 4);
        float e0, e1, e2, e3;
        unpack2(acc[m][0], e0, e1); unpack2(acc[m][1], e2, e3);
        *(float4*)(orow) = make_float4(xa.x + e0, xa.y + e1, xa.z + e2, xa.w + e3);
        unpack2(acc[m][2], e0, e1); unpack2(acc[m][3], e2, e3);
        *(float4*)(orow + 4) = make_float4(xb.x + e0, xb.y + e1, xb.z + e2, xb.w + e3);
    }
}

// =============================================================================
extern "C" void kernel_launch(void* const* d_in, const int* in_sizes, int n_in,
                              void* d_out, int out_size) {
    const float* x    = (const float*)d_in[0];
    const float* cond = (const float*)d_in[1];
    const float* P    = (const float*)d_in[2];
    const float* W    = (const float*)d_in[3];
    const float* bias = (const float*)d_in[4];
    float* out = (float*)d_out;

    float* Yg = nullptr;
    cudaGetSymbolAddress((void**)&Yg, g_Y);

    const int smem_qr   = PW * PSTR * 4;                 // 73792
    const int smem_v    = Bb * CONDD * 4;                // 73728
    const int smem_expm = (3 * MP + MPT) * 64 * 4;       // 69632
    const int smem_p1   = 3 * 64 * P1S * 4;              // 52224
    const int smem_p2   = 64 * P2SY * 4 + 64 * P2SU * 4; // 51200

    cudaFuncSetAttribute(k_panel, cudaFuncAttributeMaxDynamicSharedMemorySize, smem_qr);
    cudaFuncSetAttribute(k_v,    cudaFuncAttributeMaxDynamicSharedMemorySize, smem_v);
    cudaFuncSetAttribute(k_expm, cudaFuncAttributeMaxDynamicSharedMemorySize, smem_expm);
    cudaFuncSetAttribute(k_p1,   cudaFuncAttributeMaxDynamicSharedMemorySize, smem_p1);
    cudaFuncSetAttribute(k_p2,   cudaFuncAttributeMaxDynamicSharedMemorySize, smem_p2);

    for (int p = 0; p < 4; ++p) {
        k_panel<<<1, 256, smem_qr>>>(P, p);
        int nc = Dd - (p * PW + PW);
        if (nc > 0) k_trail<<<nc, 256>>>(p);
    }
    k_orgqr<<<Dd, 256>>>();
    k_v    <<<NSKEW / 8, 256, smem_v>>>(cond, W, bias);
    k_expm <<<Bb, 256, smem_expm>>>();
    k_p1   <<<(Bb * Tt) / 64, 256, smem_p1>>>(x, Yg);
    dim3 g2(Nn / 128, (Bb * Tt) / 64);
    k_p2   <<<g2, 256, smem_p2>>>(x, Yg, out);
}

// round 14
// speedup vs baseline: 1.0816x; 1.0816x over previous
#include <cuda_runtime.h>
#include <math.h>

#define Nn    1152
#define Dd    64
#define Bb    16
#define Tt    1024
#define NSKEW 2016
#define CONDD 1152
#define MP    68
#define MPT   68
#define P1S   68
#define P2SY  68
#define P2SU  132
#define PW    16
#define PSTR  1156   // panel column stride (float4-aligned; consecutive-lane reads conflict-free)

typedef unsigned long long ull;

// ------------------ device scratch (no allocations allowed) ------------------
__device__ __align__(16) float g_At[Dd * Nn];       // Householder vectors, column j contiguous
__device__ __align__(16) float g_tau[Dd];
__device__ __align__(16) float g_T [4 * PW * PW];   // compact-WY T per panel
__device__ __align__(16) float g_U [Nn * Dd];       // U  [n][d]
__device__ __align__(16) float g_Ut[Dd * Nn];       // U^T [d][n]
__device__ __align__(16) float g_V [Bb * NSKEW];    // silu(cond) @ W^T + b
__device__ __align__(16) float g_RmI[Bb * Dd * Dd]; // R - I per batch, row-major [d][e]
__device__ __align__(16) float g_Y [Bb * Tt * Dd];  // (X U)(R-I)

// ------------------ packed f32x2 helpers (Blackwell FFMA2) ------------------
static __device__ __forceinline__ ull pack2(float x, float y) {
    ull r; asm("mov.b64 %0, {%1, %2};" : "=l"(r) : "f"(x), "f"(y)); return r;
}
static __device__ __forceinline__ void unpack2(ull p, float& x, float& y) {
    asm("mov.b64 {%0, %1}, %2;" : "=f"(x), "=f"(y) : "l"(p));
}
static __device__ __forceinline__ ull fma2(ull a, ull b, ull c) {
    ull d; asm("fma.rn.f32x2 %0, %1, %2, %3;" : "=l"(d) : "l"(a), "l"(b), "l"(c)); return d;
}

// =============================================================================
// Kernel 1a: blocked sgeqrf (panels of 16 + compact WY), LAPACK sign convention.
// One block, 1024 threads. ONE barrier per Householder step:
//  - reflectors kept UNSCALED (v_raw, diag = alpha-beta); scaling folded into
//    coef = tau*scl^2 so updates are uniform over i >= j (no diag special-case).
//  - the warp updating column jj+1 also accumulates its new sum-of-squares and
//    pivot alpha in the same pass, then computes beta/tau/scl for the next step.
// =============================================================================
__global__ void __launch_bounds__(1024) k_geqrf(const float* __restrict__ P) {
    extern __shared__ float V[];           // [PW][PSTR] raw panel, column-major
    __shared__ float sred[32];
    __shared__ float s_ts[PW];             // tau * scl^2
    __shared__ float s_scale[PW];          // scl = 1/(alpha-beta)
    __shared__ float s_beta[PW];
    __shared__ float s_tauv[PW];
    __shared__ float Tm[PW * PW];
    __shared__ float Sm[PW * PW];
    __shared__ float W1[PW * 48];
    __shared__ float W2[PW * 48];
    const int tid = threadIdx.x, lane = tid & 31, wid = tid >> 5;

    // load P^T: g_At[j][i] = P[i][j]
    for (int idx = tid; idx < Nn * Dd; idx += 1024) {
        int i = idx >> 6, j = idx & 63;
        g_At[j * Nn + i] = P[idx];
    }
    __syncthreads();

    for (int p = 0; p < 4; ++p) {
        const int j0 = p * PW;

        // ---- load panel into smem (float4) ----
        for (int f = tid; f < PW * (Nn / 4); f += 1024) {
            int c = f / (Nn / 4), i4 = f - c * (Nn / 4);
            ((float4*)(V + c * PSTR))[i4] =
                ((const float4*)(g_At + (size_t)(j0 + c) * Nn))[i4];
        }
        __syncthreads();

        // ---- prologue: reflector params for panel column 0 ----
        {
            float ssl = 0.f;
            for (int i = j0 + 1 + tid; i < Nn; i += 1024) { float a = V[i]; ssl += a * a; }
            #pragma unroll
            for (int o = 16; o; o >>= 1) ssl += __shfl_xor_sync(0xffffffffu, ssl, o);
            if (lane == 0) sred[wid] = ssl;
            __syncthreads();
            if (wid == 0) {
                float qv = sred[lane];
                #pragma unroll
                for (int o = 16; o; o >>= 1) qv += __shfl_xor_sync(0xffffffffu, qv, o);
                if (lane == 0) {
                    float alpha = V[j0];
                    float nrm = sqrtf(alpha * alpha + qv);
                    float beta = (alpha >= 0.f) ? -nrm : nrm;   // LAPACK
                    float tau = (beta - alpha) / beta;
                    float scl = 1.f / (alpha - beta);
                    s_ts[0] = tau * scl * scl; s_scale[0] = scl;
                    s_beta[0] = beta; s_tauv[0] = tau;
                    V[j0] = alpha - beta;                        // v_raw diag
                }
            }
        }

        // ---- 15 fused steps: apply H_jj to panel cols jj+1..15; warp 0 also
        //      produces reflector params for column jj+1 ----
        for (int jj = 0; jj < PW - 1; ++jj) {
            __syncthreads();                       // params + previous updates ready
            const int j = j0 + jj;
            const int kcol = jj + 1 + wid;
            if (kcol < PW) {
                const float* vr = V + jj * PSTR;
                float* ck = V + kcol * PSTR;
                float dp = 0.f;
                for (int i = j + lane; i < Nn; i += 32) dp += vr[i] * ck[i];
                #pragma unroll
                for (int o = 16; o; o >>= 1) dp += __shfl_xor_sync(0xffffffffu, dp, o);
                const float coef = s_ts[jj] * dp;
                if (wid == 0) {
                    const int jn = j + 1;
                    float ssn = 0.f, alv = 0.f;
                    for (int i = j + lane; i < Nn; i += 32) {
                        float nv = ck[i] - coef * vr[i];
                        ck[i] = nv;
                        if (i > jn) ssn += nv * nv;
                        if (i == jn) alv = nv;
                    }
                    #pragma unroll
                    for (int o = 16; o; o >>= 1) ssn += __shfl_xor_sync(0xffffffffu, ssn, o);
                    #pragma unroll
                    for (int o = 16; o; o >>= 1) alv += __shfl_xor_sync(0xffffffffu, alv, o);
                    if (lane == 0) {
                        float nrm = sqrtf(alv * alv + ssn);
                        float beta = (alv >= 0.f) ? -nrm : nrm;   // LAPACK
                        float tau = (beta - alv) / beta;
                        float scl = 1.f / (alv - beta);
                        s_ts[jj + 1] = tau * scl * scl; s_scale[jj + 1] = scl;
                        s_beta[jj + 1] = beta; s_tauv[jj + 1] = tau;
                        ck[jn] = alv - beta;                      // v_raw diag
                    }
                } else {
                    for (int i = j + lane; i < Nn; i += 32) ck[i] -= coef * vr[i];
                }
            }
        }
        __syncthreads();

        // ---- write back (R + scaled reflectors) and normalize smem V for WY ----
        for (int idx = tid; idx < PW * Nn; idx += 1024) {
            int c = idx / Nn, i = idx - c * Nn;
            int diag = j0 + c;
            float val = V[c * PSTR + i];
            float outv, smv;
            if (i > diag)       { outv = val * s_scale[c]; smv = outv; }
            else if (i == diag) { outv = s_beta[c]; smv = 1.f; g_tau[diag] = s_tauv[c]; }
            else                { outv = val; smv = (i >= j0) ? 0.f : val; }
            g_At[(size_t)(j0 + c) * Nn + i] = outv;
            V[c * PSTR + i] = smv;
        }
        if (tid < PW * PW) { Tm[tid] = 0.f; Sm[tid] = 0.f; }
        __syncthreads();

        // ---- S[a][b] = v_a . v_b (a < b) ----
        for (int pr = wid; pr < PW * PW; pr += 32) {
            int a = pr >> 4, b2 = pr & 15;
            if (a < b2) {
                float dp = 0.f;
                for (int i = j0 + a + lane; i < Nn; i += 32)
                    dp += V[a * PSTR + i] * V[b2 * PSTR + i];
                #pragma unroll
                for (int o = 16; o; o >>= 1) dp += __shfl_xor_sync(0xffffffffu, dp, o);
                if (lane == 0) Sm[a * PW + b2] = dp;
            }
        }
        __syncthreads();

        // ---- build T (dlarft forward columnwise), warp 0 ----
        if (wid == 0) {
            for (int jj = 0; jj < PW; ++jj) {
                float t = 0.f;
                if (lane < jj) {
                    float acc = 0.f;
                    for (int m = 0; m < jj; ++m) acc += Tm[lane * PW + m] * Sm[m * PW + jj];
                    t = -s_tauv[jj] * acc;
                }
                __syncwarp();
                if (lane < jj) Tm[lane * PW + jj] = t;
                if (lane == jj) Tm[jj * PW + jj] = s_tauv[jj];
                __syncwarp();
            }
        }
        __syncthreads();
        if (tid < PW * PW) g_T[p * PW * PW + tid] = Tm[tid];

        // ---- trailing update: C <- C - V * T^T * (V^T C) ----
        const int nc = Dd - (j0 + PW);
        if (nc > 0) {
            for (int pr = wid; pr < PW * nc; pr += 32) {
                int a = pr / nc, k = pr - a * nc;
                const float* ck = g_At + (size_t)(j0 + PW + k) * Nn;
                float dp = 0.f;
                for (int i = j0 + a + lane; i < Nn; i += 32)
                    dp += V[a * PSTR + i] * ck[i];
                #pragma unroll
                for (int o = 16; o; o >>= 1) dp += __shfl_xor_sync(0xffffffffu, dp, o);
                if (lane == 0) W1[a * 48 + k] = dp;
            }
            __syncthreads();
            for (int idx = tid; idx < PW * nc; idx += 1024) {
                int b2 = idx / nc, k = idx - b2 * nc;
                float acc = 0.f;
                for (int a = 0; a <= b2; ++a) acc += Tm[a * PW + b2] * W1[a * 48 + k];
                W2[b2 * 48 + k] = acc;
            }
            __syncthreads();
            for (int i = j0 + tid; i < Nn; i += 1024) {
                float vv[PW];
                #pragma unroll
                for (int a = 0; a < PW; ++a) vv[a] = V[a * PSTR + i];
                for (int k = 0; k < nc; ++k) {
                    float acc = 0.f;
                    #pragma unroll
                    for (int a = 0; a < PW; ++a) acc += vv[a] * W2[a * 48 + k];
                    g_At[(size_t)(j0 + PW + k) * Nn + i] -= acc;
                }
            }
            __syncthreads();
        }
    }
}

// =============================================================================
// Kernel 1b: sorgqr, one block per Q column. Panels cached in smem; boundary
// chain runs barrier-free in warp 0; WY applies from smem with the 16x16
// triangle fixed to explicit 0/1 (uniform dots/updates).
// =============================================================================
__global__ void __launch_bounds__(256) k_orgqr() {
    extern __shared__ float sm[];
    float* q  = sm;                // [Nn]
    float* Vp = sm + Nn;           // [PW][PSTR]
    __shared__ float w[PW], w2[PW], staus[PW];
    const int tid = threadIdx.x, lane = tid & 31, wid = tid >> 5;
    const int k = blockIdx.x;
    const int pk = k >> 4;

    for (int i = tid; i < Nn; i += 256) q[i] = (i == k) ? 1.f : 0.f;

    for (int p = pk; p >= 0; --p) {
        const int j0 = p * PW;
        __syncthreads();
        // load panel (float4) + taus
        for (int f = tid; f < PW * (Nn / 4); f += 256) {
            int c = f / (Nn / 4), i4 = f - c * (Nn / 4);
            ((float4*)(Vp + c * PSTR))[i4] =
                ((const float4*)(g_At + (size_t)(j0 + c) * Nn))[i4];
        }
        if (tid < PW) staus[tid] = g_tau[j0 + tid];
        __syncthreads();
        // fix 16x16 triangle: zeros above diag, unit diag
        {
            int c = tid >> 4, io = tid & 15;
            if (tid < 256) {
                float* vv = Vp + c * PSTR + j0 + io;
                if (io < c)       *vv = 0.f;
                else if (io == c) *vv = 1.f;
            }
        }
        __syncthreads();

        if (p == pk) {
            if (wid == 0) {
                for (int j = k; j >= j0; --j) {
                    const float* v = Vp + (j - j0) * PSTR;
                    float dp = 0.f;
                    for (int i = j + lane; i < Nn; i += 32) dp += v[i] * q[i];
                    #pragma unroll
                    for (int o = 16; o; o >>= 1) dp += __shfl_xor_sync(0xffffffffu, dp, o);
                    const float coef = staus[j - j0] * dp;
                    for (int i = j + lane; i < Nn; i += 32) q[i] -= coef * v[i];
                }
            }
        } else {
            for (int a = wid; a < PW; a += 8) {
                const float* v = Vp + a * PSTR;
                float dp = 0.f;
                for (int i = j0 + a + lane; i < Nn; i += 32) dp += v[i] * q[i];
                #pragma unroll
                for (int o = 16; o; o >>= 1) dp += __shfl_xor_sync(0xffffffffu, dp, o);
                if (lane == 0) w[a] = dp;
            }
            __syncthreads();
            if (tid < PW) {
                const float* Tp = g_T + p * PW * PW;
                float acc = 0.f;
                for (int b2 = tid; b2 < PW; ++b2) acc += Tp[tid * PW + b2] * w[b2];
                w2[tid] = acc;
            }
            __syncthreads();
            for (int i = j0 + tid; i < Nn; i += 256) {
                float acc = 0.f;
                #pragma unroll
                for (int a = 0; a < PW; ++a) acc += Vp[a * PSTR + i] * w2[a];
                q[i] -= acc;
            }
        }
    }
    __syncthreads();
    for (int i = tid; i < Nn; i += 256) {
        float val = q[i];
        g_Ut[k * Nn + i] = val;
        g_U[i * Dd + k]  = val;
    }
}

// =============================================================================
// Kernel 2: g_V[b][r] = dot(W[r], silu(cond[b])) + bias[r]
// =============================================================================
__global__ void __launch_bounds__(256) k_v(const float* __restrict__ cond,
                                           const float* __restrict__ W,
                                           const float* __restrict__ bias) {
    extern __shared__ float S[];   // [16][1152] silu(cond)
    const int tid = threadIdx.x, lane = tid & 31, wid = tid >> 5;
    for (int i = tid; i < Bb * CONDD; i += 256) {
        float c = cond[i];
        S[i] = c / (1.f + expf(-c));
    }
    __syncthreads();

    int r = blockIdx.x * 8 + wid;
    const float* wr = W + (size_t)r * CONDD;
    float acc[16];
    #pragma unroll
    for (int b = 0; b < 16; b++) acc[b] = 0.f;
    for (int c0 = 0; c0 < CONDD; c0 += 32) {
        float wv = wr[c0 + lane];
        #pragma unroll
        for (int b = 0; b < 16; b++) acc[b] += wv * S[b * CONDD + c0 + lane];
    }
    #pragma unroll
    for (int b = 0; b < 16; b++) {
        #pragma unroll
        for (int o = 16; o; o >>= 1) acc[b] += __shfl_xor_sync(0xffffffffu, acc[b], o);
    }
    if (lane == 0) {
        float bv = bias[r];
        #pragma unroll
        for (int b = 0; b < 16; b++) g_V[b * NSKEW + r] = acc[b] + bv;
    }
}

// =============================================================================
// Kernel 3: expm per batch (scaling & squaring + Taylor-Horner K=8).
// 16 blocks x 256 threads, 4x4 register tile per thread, FFMA2 inner loops.
// =============================================================================
static __device__ __forceinline__ void mm_horner(float* __restrict__ out,
                                                 const float* __restrict__ As,
                                                 const float* __restrict__ X,
                                                 float invk, int r0, int c0) {
    ull acc[4][2] = {};
    #pragma unroll 4
    for (int d = 0; d < 64; ++d) {
        float4 a4 = *(const float4*)(As + d * MP + r0);        // As[d][r] = -A[r][d]
        ulonglong2 bv = *(const ulonglong2*)(X + d * MP + c0);
        ull a0 = pack2(a4.x, a4.x), a1 = pack2(a4.y, a4.y);
        ull a2 = pack2(a4.z, a4.z), a3 = pack2(a4.w, a4.w);
        acc[0][0] = fma2(a0, bv.x, acc[0][0]); acc[0][1] = fma2(a0, bv.y, acc[0][1]);
        acc[1][0] = fma2(a1, bv.x, acc[1][0]); acc[1][1] = fma2(a1, bv.y, acc[1][1]);
        acc[2][0] = fma2(a2, bv.x, acc[2][0]); acc[2][1] = fma2(a2, bv.y, acc[2][1]);
        acc[3][0] = fma2(a3, bv.x, acc[3][0]); acc[3][1] = fma2(a3, bv.y, acc[3][1]);
    }
    const float nk = -invk;   // negate to undo the transposed-skew sign
    #pragma unroll
    for (int m = 0; m < 4; ++m) {
        float s0, s1, s2, s3;
        unpack2(acc[m][0], s0, s1);
        unpack2(acc[m][1], s2, s3);
        float4 o;
        o.x = nk * s0 + ((r0 + m == c0 + 0) ? 1.f : 0.f);
        o.y = nk * s1 + ((r0 + m == c0 + 1) ? 1.f : 0.f);
        o.z = nk * s2 + ((r0 + m == c0 + 2) ? 1.f : 0.f);
        o.w = nk * s3 + ((r0 + m == c0 + 3) ? 1.f : 0.f);
        *(float4*)(out + (r0 + m) * MP + c0) = o;
    }
}

static __device__ __forceinline__ void mm_sq(float* __restrict__ out,
                                             const float* __restrict__ XT,
                                             const float* __restrict__ X,
                                             int r0, int c0) {
    ull acc[4][2] = {};
    #pragma unroll 4
    for (int d = 0; d < 64; ++d) {
        float4 a4 = *(const float4*)(XT + d * MPT + r0);       // X[r0..r0+3][d]
        ulonglong2 bv = *(const ulonglong2*)(X + d * MP + c0);
        ull a0 = pack2(a4.x, a4.x), a1 = pack2(a4.y, a4.y);
        ull a2 = pack2(a4.z, a4.z), a3 = pack2(a4.w, a4.w);
        acc[0][0] = fma2(a0, bv.x, acc[0][0]); acc[0][1] = fma2(a0, bv.y, acc[0][1]);
        acc[1][0] = fma2(a1, bv.x, acc[1][0]); acc[1][1] = fma2(a1, bv.y, acc[1][1]);
        acc[2][0] = fma2(a2, bv.x, acc[2][0]); acc[2][1] = fma2(a2, bv.y, acc[2][1]);
        acc[3][0] = fma2(a3, bv.x, acc[3][0]); acc[3][1] = fma2(a3, bv.y, acc[3][1]);
    }
    #pragma unroll
    for (int m = 0; m < 4; ++m) {
        float s0, s1, s2, s3;
        unpack2(acc[m][0], s0, s1);
        unpack2(acc[m][1], s2, s3);
        *(float4*)(out + (r0 + m) * MP + c0) = make_float4(s0, s1, s2, s3);
    }
}

__global__ void __launch_bounds__(256) k_expm() {
    extern __shared__ float sm[];
    float* As = sm;                     // 64*68
    float* X0 = As + 64 * MP;
    float* X1 = X0 + 64 * MP;
    float* XT = X1 + 64 * MP;
    __shared__ float rowsum[64];
    __shared__ int s_s;
    const int tid = threadIdx.x;
    const int r0 = (tid >> 4) * 4, c0 = (tid & 15) * 4;
    const int b = blockIdx.x;
    const float* v = g_V + b * NSKEW;

    for (int t = tid; t < 4096; t += 256) {
        int i = t >> 6, j = t & 63;
        float val = 0.f;
        if (i < j)      val =  v[i * (127 - i) / 2 + (j - i - 1)];
        else if (i > j) val = -v[j * (127 - j) / 2 + (i - j - 1)];
        As[i * MP + j] = val;
    }
    __syncthreads();
    if (tid < 64) {
        float s = 0.f;
        for (int j = 0; j < 64; j++) s += fabsf(As[tid * MP + j]);
        rowsum[tid] = s;
    }
    __syncthreads();
    if (tid == 0) {
        float nrm = 0.f;
        for (int i = 0; i < 64; i++) nrm = fmaxf(nrm, rowsum[i]);
        int s = 0; float nn = nrm;
        while (nn > 0.5f && s < 40) { nn *= 0.5f; s++; }
        s_s = s;
    }
    __syncthreads();
    const int s = s_s;
    const float sc = exp2f((float)(-s));
    for (int t = tid; t < 4096; t += 256) { int i = t >> 6, j = t & 63; As[i * MP + j] *= sc; }
    __syncthreads();

    for (int t = tid; t < 4096; t += 256) {
        int i = t >> 6, j = t & 63;
        X0[i * MP + j] = ((i == j) ? 1.f : 0.f) + As[i * MP + j] * 0.125f;
    }
    float* Xa = X0; float* Xb = X1;
    for (int k = 7; k >= 1; --k) {
        __syncthreads();
        mm_horner(Xb, As, Xa, 1.f / (float)k, r0, c0);
        float* t = Xa; Xa = Xb; Xb = t;
    }
    for (int q = 0; q < s; q++) {
        __syncthreads();
        for (int t = tid; t < 4096; t += 256) {      // XT[j][i] = Xa[i][j]
            int i = t >> 6, j = t & 63;
            XT[j * MPT + i] = Xa[i * MP + j];
        }
        __syncthreads();
        mm_sq(Xb, XT, Xa, r0, c0);
        float* t = Xa; Xa = Xb; Xb = t;
    }
    __syncthreads();
    for (int t = tid; t < 4096; t += 256) {
        int i = t >> 6, j = t & 63;
        g_RmI[b * 4096 + t] = Xa[i * MP + j] - ((i == j) ? 1.f : 0.f);
    }
}

// =============================================================================
// Kernel 4: Y = (X U)(R - I).  64-row tiles, 256 blocks, 256 threads.
// =============================================================================
__global__ void __launch_bounds__(256) k_p1(const float* __restrict__ X,
                                            float* __restrict__ Y) {
    extern __shared__ float sm[];
    float* XsT = sm;                 // [64][68]  XsT[k][r]
    float* Us  = sm + 64 * P1S;      // [64][68]  Us[k][c]
    float* Ms  = Us + 64 * P1S;      // [64][68]  Ms[d][e]

    const int tid = threadIdx.x;
    const int rg = tid >> 4, cg = tid & 15;
    const int r0 = rg * 4, c0 = cg * 4;
    const size_t rowbase = (size_t)blockIdx.x * 64;
    const float* Xg = X + rowbase * Nn;
    const int b = blockIdx.x >> 4;

    const float* Mg = g_RmI + b * 4096;
    for (int i = tid; i < 4096; i += 256) {
        int d = i >> 6, e = i & 63;
        Ms[d * P1S + e] = Mg[i];
    }

    ull acc[4][2] = {};
    for (int kc = 0; kc < Nn; kc += 64) {
        __syncthreads();
        #pragma unroll
        for (int it = 0; it < 4; ++it) {
            int f4 = tid + 256 * it;
            int r  = f4 >> 4;
            int kq = (f4 & 15) * 4;
            float4 v = *(const float4*)(Xg + (size_t)r * Nn + kc + kq);
            XsT[(kq + 0) * P1S + r] = v.x;
            XsT[(kq + 1) * P1S + r] = v.y;
            XsT[(kq + 2) * P1S + r] = v.z;
            XsT[(kq + 3) * P1S + r] = v.w;
        }
        #pragma unroll
        for (int it = 0; it < 4; ++it) {
            int f4 = tid + 256 * it;
            int kk = f4 >> 4;
            int dq = (f4 & 15) * 4;
            float4 v = *(const float4*)(g_U + (size_t)(kc + kk) * Dd + dq);
            *(float4*)(Us + kk * P1S + dq) = v;
        }
        __syncthreads();
        #pragma unroll 4
        for (int k = 0; k < 64; ++k) {
            float4 xv = *(const float4*)(XsT + k * P1S + r0);
            ulonglong2 uv = *(const ulonglong2*)(Us + k * P1S + c0);
            ull x0 = pack2(xv.x, xv.x), x1 = pack2(xv.y, xv.y);
            ull x2 = pack2(xv.z, xv.z), x3 = pack2(xv.w, xv.w);
            acc[0][0] = fma2(x0, uv.x, acc[0][0]); acc[0][1] = fma2(x0, uv.y, acc[0][1]);
            acc[1][0] = fma2(x1, uv.x, acc[1][0]); acc[1][1] = fma2(x1, uv.y, acc[1][1]);
            acc[2][0] = fma2(x2, uv.x, acc[2][0]); acc[2][1] = fma2(x2, uv.y, acc[2][1]);
            acc[3][0] = fma2(x3, uv.x, acc[3][0]); acc[3][1] = fma2(x3, uv.y, acc[3][1]);
        }
    }
    __syncthreads();
    float* ZsT = XsT;
    #pragma unroll
    for (int m = 0; m < 4; ++m) {
        float a0, a1;
        unpack2(acc[m][0], a0, a1);
        ZsT[(c0 + 0) * P1S + r0 + m] = a0;
        ZsT[(c0 + 1) * P1S + r0 + m] = a1;
        unpack2(acc[m][1], a0, a1);
        ZsT[(c0 + 2) * P1S + r0 + m] = a0;
        ZsT[(c0 + 3) * P1S + r0 + m] = a1;
    }
    __syncthreads();
    ull yac[4][2] = {};
    #pragma unroll 4
    for (int d = 0; d < 64; ++d) {
        float4 zv = *(const float4*)(ZsT + d * P1S + r0);
        ulonglong2 mv = *(const ulonglong2*)(Ms + d * P1S + c0);
        ull z0 = pack2(zv.x, zv.x), z1 = pack2(zv.y, zv.y);
        ull z2 = pack2(zv.z, zv.z), z3 = pack2(zv.w, zv.w);
        yac[0][0] = fma2(z0, mv.x, yac[0][0]); yac[0][1] = fma2(z0, mv.y, yac[0][1]);
        yac[1][0] = fma2(z1, mv.x, yac[1][0]); yac[1][1] = fma2(z1, mv.y, yac[1][1]);
        yac[2][0] = fma2(z2, mv.x, yac[2][0]); yac[2][1] = fma2(z2, mv.y, yac[2][1]);
        yac[3][0] = fma2(z3, mv.x, yac[3][0]); yac[3][1] = fma2(z3, mv.y, yac[3][1]);
    }
    #pragma unroll
    for (int m = 0; m < 4; ++m) {
        float e0, e1, e2, e3;
        unpack2(yac[m][0], e0, e1);
        unpack2(yac[m][1], e2, e3);
        *(float4*)(Y + (rowbase + r0 + m) * Dd + c0) = make_float4(e0, e1, e2, e3);
    }
}

// =============================================================================
// Kernel 5: out = X + Y U^T.  Block tile 64 rows x 128 n-cols; grid (9, 256).
// =============================================================================
__global__ void __launch_bounds__(256) k_p2(const float* __restrict__ X,
                                            const float* __restrict__ Y,
                                            float* __restrict__ out) {
    extern __shared__ float sm[];
    float* YsT = sm;                 // [64][68]
    float* Uts = sm + 64 * P2SY;     // [64][132]

    const int tid = threadIdx.x;
    const int rg = tid >> 4, cg = tid & 15;
    const int r0 = rg * 4;
    const int n0 = cg * 8;
    const size_t rowbase = (size_t)blockIdx.y * 64;
    const int nbase = blockIdx.x * 128;

    #pragma unroll
    for (int it = 0; it < 4; ++it) {
        int f4 = tid + 256 * it;
        int r  = f4 >> 4;
        int dq = (f4 & 15) * 4;
        float4 v = *(const float4*)(Y + (rowbase + r) * Dd + dq);
        YsT[(dq + 0) * P2SY + r] = v.x;
        YsT[(dq + 1) * P2SY + r] = v.y;
        YsT[(dq + 2) * P2SY + r] = v.z;
        YsT[(dq + 3) * P2SY + r] = v.w;
    }
    #pragma unroll
    for (int it = 0; it < 8; ++it) {
        int f4 = tid + 256 * it;
        int d  = f4 >> 5;
        int nq = (f4 & 31) * 4;
        float4 v = *(const float4*)(g_Ut + (size_t)d * Nn + nbase + nq);
        *(float4*)(Uts + d * P2SU + nq) = v;
    }
    __syncthreads();

    ull acc[4][4] = {};
    #pragma unroll 4
    for (int d = 0; d < 64; ++d) {
        float4 yv = *(const float4*)(YsT + d * P2SY + r0);
        ulonglong2 u0 = *(const ulonglong2*)(Uts + d * P2SU + n0);
        ulonglong2 u1 = *(const ulonglong2*)(Uts + d * P2SU + n0 + 4);
        ull y0 = pack2(yv.x, yv.x), y1 = pack2(yv.y, yv.y);
        ull y2 = pack2(yv.z, yv.z), y3 = pack2(yv.w, yv.w);
        acc[0][0] = fma2(y0, u0.x, acc[0][0]); acc[0][1] = fma2(y0, u0.y, acc[0][1]);
        acc[0][2] = fma2(y0, u1.x, acc[0][2]); acc[0][3] = fma2(y0, u1.y, acc[0][3]);
        acc[1][0] = fma2(y1, u0.x, acc[1][0]); acc[1][1] = fma2(y1, u0.y, acc[1][1]);
        acc[1][2] = fma2(y1, u1.x, acc[1][2]); acc[1][3] = fma2(y1, u1.y, acc[1][3]);
        acc[2][0] = fma2(y2, u0.x, acc[2][0]); acc[2][1] = fma2(y2, u0.y, acc[2][1]);
        acc[2][2] = fma2(y2, u1.x, acc[2][2]); acc[2][3] = fma2(y2, u1.y, acc[2][3]);
        acc[3][0] = fma2(y3, u0.x, acc[3][0]); acc[3][1] = fma2(y3, u0.y, acc[3][1]);
        acc[3][2] = fma2(y3, u1.x, acc[3][2]); acc[3][3] = fma2(y3, u1.y, acc[3][3]);
    }

    #pragma unroll
    for (int m = 0; m < 4; ++m) {
        const size_t row = rowbase + r0 + m;
        const float* xr = X + row * Nn + nbase + n0;
        float* orow = out + row * Nn + nbase + n0;
        float4 xa = *(const float4*)(xr);
        float4 xb = *(const float4*)(xr + 4);
        float e0, e1, e2, e3;
        unpack2(acc[m][0], e0, e1); unpack2(acc[m][1], e2, e3);
        *(float4*)(orow) = make_float4(xa.x + e0, xa.y + e1, xa.z + e2, xa.w + e3);
        unpack2(acc[m][2], e0, e1); unpack2(acc[m][3], e2, e3);
        *(float4*)(orow + 4) = make_float4(xb.x + e0, xb.y + e1, xb.z + e2, xb.w + e3);
    }
}

// =============================================================================
extern "C" void kernel_launch(void* const* d_in, const int* in_sizes, int n_in,
                              void* d_out, int out_size) {
    const float* x    = (const float*)d_in[0];
    const float* cond = (const float*)d_in[1];
    const float* P    = (const float*)d_in[2];
    const float* W    = (const float*)d_in[3];
    const float* bias = (const float*)d_in[4];
    float* out = (float*)d_out;

    float* Yg = nullptr;
    cudaGetSymbolAddress((void**)&Yg, g_Y);

    const int smem_qr    = PW * PSTR * 4;                 // 73984
    const int smem_orgqr = (Nn + PW * PSTR) * 4;          // 78592
    const int smem_v     = Bb * CONDD * 4;                // 73728
    const int smem_expm  = (3 * MP + MPT) * 64 * 4;       // 69632
    const int smem_p1    = 3 * 64 * P1S * 4;              // 52224
    const int smem_p2    = 64 * P2SY * 4 + 64 * P2SU * 4; // 51200

    cudaFuncSetAttribute(k_geqrf, cudaFuncAttributeMaxDynamicSharedMemorySize, smem_qr);
    cudaFuncSetAttribute(k_orgqr, cudaFuncAttributeMaxDynamicSharedMemorySize, smem_orgqr);
    cudaFuncSetAttribute(k_v,    cudaFuncAttributeMaxDynamicSharedMemorySize, smem_v);
    cudaFuncSetAttribute(k_expm, cudaFuncAttributeMaxDynamicSharedMemorySize, smem_expm);
    cudaFuncSetAttribute(k_p1,   cudaFuncAttributeMaxDynamicSharedMemorySize, smem_p1);
    cudaFuncSetAttribute(k_p2,   cudaFuncAttributeMaxDynamicSharedMemorySize, smem_p2);

    k_v    <<<NSKEW / 8, 256, smem_v>>>(cond, W, bias);
    k_geqrf<<<1, 1024, smem_qr>>>(P);
    k_expm <<<Bb, 256, smem_expm>>>();
    k_orgqr<<<Dd, 256, smem_orgqr>>>();
    k_p1   <<<(Bb * Tt) / 64, 256, smem_p1>>>(x, Yg);
    dim3 g2(Nn / 128, (Bb * Tt) / 64);
    k_p2   <<<g2, 256, smem_p2>>>(x, Yg, out);
}